// round 7
// baseline (speedup 1.0000x reference)
#include <cuda_runtime.h>
#include <cstdint>

typedef unsigned long long ull;

#define NN 512
#define F 16
#define T 64          // tile edge
#define TS 68         // staged slice stride (floats)
#define TT 65         // sT stride: odd => conflict-free column reads
#define NTHREADS 256

struct ull2_t { ull x, y; };

__device__ __forceinline__ ull pack2(float lo, float hi) {
    ull r;
    asm("mov.b64 %0, {%1, %2};" : "=l"(r) : "f"(lo), "f"(hi));
    return r;
}
__device__ __forceinline__ void unpack2(ull v, float& lo, float& hi) {
    asm("mov.b64 {%0, %1}, %2;" : "=f"(lo), "=f"(hi) : "l"(v));
}
__device__ __forceinline__ ull fma2(ull a, ull b, ull c) {
    ull d;
    asm("fma.rn.f32x2 %0, %1, %2, %3;" : "=l"(d) : "l"(a), "l"(b), "l"(c));
    return d;
}
__device__ __forceinline__ ull add2(ull a, ull b) {
    ull d;
    asm("add.rn.f32x2 %0, %1, %2;" : "=l"(d) : "l"(a), "l"(b));
    return d;
}

// clip(exp(-0.1*sqrt(max(v, 1e-6))), 0, 1)
__device__ __forceinline__ float gauss1(float v) {
    float t = fmaxf(v, 1e-6f);
    float d;
    asm("sqrt.approx.f32 %0, %1;" : "=f"(d) : "f"(t));
    float x = d * -0.14426950408889634f;   // -0.1 * log2(e)
    float e;
    asm("ex2.approx.f32 %0, %1;" : "=f"(e) : "f"(x));
    return fminf(e, 1.0f);                 // always >= 0
}

__global__ void __launch_bounds__(NTHREADS, 2)
npg_sym_kernel(const float* __restrict__ x, const float* __restrict__ msk,
               float* __restrict__ out) {
    __shared__ __align__(16) float sRow[F][TS];   // row slice, f-major
    __shared__ __align__(16) float sCol[F][TS];   // col slice, f-major
    __shared__ __align__(16) float sNaR[T];
    __shared__ __align__(16) float sNaC[T];
    __shared__ __align__(16) float sT[T][TT];     // tile for mirror transpose

    const int tid = threadIdx.x;
    const int bk  = blockIdx.y;

    // decode upper-triangular tile pair (ti <= tj), 36 tiles of 8x8 grid
    int t = blockIdx.x, ti = 0;
    while (t >= 8 - ti) { t -= 8 - ti; ++ti; }
    const int tj = ti + t;
    const int rbase = ti * T;
    const int cbase = tj * T;

    // ---- stage both 64x16 slices (A = x * msk), f-major ----
    {
        const int n  = tid >> 2;            // 0..63
        const int f0 = (tid & 3) << 2;      // 0,4,8,12
        const float4* xb = reinterpret_cast<const float4*>(x + (size_t)bk * NN * F);
        const float*  mb = msk + (size_t)bk * NN;

        float4 v = __ldg(&xb[(rbase + n) * (F / 4) + (f0 >> 2)]);
        float  m = __ldg(&mb[rbase + n]);
        sRow[f0 + 0][n] = v.x * m;
        sRow[f0 + 1][n] = v.y * m;
        sRow[f0 + 2][n] = v.z * m;
        sRow[f0 + 3][n] = v.w * m;

        float4 w  = __ldg(&xb[(cbase + n) * (F / 4) + (f0 >> 2)]);
        float  mc = __ldg(&mb[cbase + n]);
        sCol[f0 + 0][n] = w.x * mc;
        sCol[f0 + 1][n] = w.y * mc;
        sCol[f0 + 2][n] = w.z * mc;
        sCol[f0 + 3][n] = w.w * mc;
    }
    __syncthreads();

    // ---- na for both slices ----
    if (tid < T) {
        float s = 0.f;
        #pragma unroll
        for (int f = 0; f < F; f++) { float a = sRow[f][tid]; s = fmaf(a, a, s); }
        sNaR[tid] = s;
    } else if (tid < 2 * T) {
        int n = tid - T;
        float s = 0.f;
        #pragma unroll
        for (int f = 0; f < F; f++) { float a = sCol[f][n]; s = fmaf(a, a, s); }
        sNaC[n] = s;
    }
    __syncthreads();

    const int cx = tid & 15;      // 16 col-threads, 4 adjacent cols each
    const int ry = tid >> 4;      // 16 row groups, 4 rows each
    const int c0 = 4 * cx;

    // ---- cache 4 cols x 16 f as packed pairs (no movs: ull2 loads) ----
    ull ccA[F], ccB[F];
    #pragma unroll
    for (int f = 0; f < F; f++) {
        ull2_t u = *reinterpret_cast<const ull2_t*>(&sCol[f][c0]);
        ccA[f] = u.x;
        ccB[f] = u.y;
    }
    ull nacA, nacB;
    {
        ull2_t u = *reinterpret_cast<const ull2_t*>(&sNaC[c0]);
        nacA = u.x;
        nacB = u.y;
    }

    float* outb = out + (size_t)bk * NN * NN;
    const ull NEG2 = pack2(-2.f, -2.f);

    // ---- compute 4 rows x 4 cols, write straight + stash for mirror ----
    #pragma unroll 1
    for (int i = 0; i < 4; i++) {
        const int r = 4 * ry + i;
        const float nar = sNaR[r];
        const ull nar2 = pack2(nar, nar);

        ull aA = 0ULL, aB = 0ULL;
        #pragma unroll
        for (int f = 0; f < F; f++) {
            float a = sRow[f][r];          // 2-way broadcast LDS per warp
            ull a2 = pack2(a, a);
            aA = fma2(a2, ccA[f], aA);
            aB = fma2(a2, ccB[f], aB);
        }

        ull vA = fma2(aA, NEG2, add2(nar2, nacA));   // na_r - 2*dot + na_c
        ull vB = fma2(aB, NEG2, add2(nar2, nacB));
        float v0, v1, v2, v3;
        unpack2(vA, v0, v1);
        unpack2(vB, v2, v3);

        float4 o;
        o.x = gauss1(v0);
        o.y = gauss1(v1);
        o.z = gauss1(v2);
        o.w = gauss1(v3);

        // straight write (coalesced STG.128)
        *reinterpret_cast<float4*>(&outb[(size_t)(rbase + r) * NN + cbase + c0]) = o;

        // stash for mirror (scalar STS, ~2-way conflict)
        sT[r][c0 + 0] = o.x;
        sT[r][c0 + 1] = o.y;
        sT[r][c0 + 2] = o.z;
        sT[r][c0 + 3] = o.w;
    }

    // ---- mirror write for off-diagonal tiles (coalesced via smem transpose) ----
    if (ti != tj) {
        __syncthreads();
        const int c   = tid >> 2;     // 0..63  (column of tile = mirror row)
        const int seg = tid & 3;      // 16-element segment of mirror row
        float* dst = outb + (size_t)(cbase + c) * NN + rbase + seg * 16;
        #pragma unroll
        for (int k = 0; k < 4; k++) {
            const int rr = seg * 16 + 4 * k;
            float4 w;
            w.x = sT[rr + 0][c];      // stride-65: conflict-free column read
            w.y = sT[rr + 1][c];
            w.z = sT[rr + 2][c];
            w.w = sT[rr + 3][c];
            *reinterpret_cast<float4*>(&dst[4 * k]) = w;
        }
    }
}

extern "C" void kernel_launch(void* const* d_in, const int* in_sizes, int n_in,
                              void* d_out, int out_size) {
    const float* x   = (const float*)d_in[0];   // (8,64,512,16)
    const float* msk = (const float*)d_in[1];   // (8,64,512,1)
    float* out = (float*)d_out;                 // (8,64,512,512,1)

    int bk_total = in_sizes[0] / (NN * F);      // 512
    dim3 grid(36, bk_total);                    // 36 upper-tri tiles x 512 (b,bin)
    npg_sym_kernel<<<grid, NTHREADS>>>(x, msk, out);
}

// round 8
// speedup vs baseline: 1.4837x; 1.4837x over previous
#include <cuda_runtime.h>
#include <cstdint>

typedef unsigned long long ull;

#define NN 512
#define F 16
#define TE 128            // tile edge
#define RDS 260           // sRowD stride (floats), duplicated (a,a) storage
#define CS 132            // sCol stride (floats)
#define XS 133            // transpose strip stride: 5r+c bank pattern, conflict-free
#define NTHREADS 256

struct ull2_t { ull x, y; };

__device__ __forceinline__ ull pack2(float lo, float hi) {
    ull r;
    asm("mov.b64 %0, {%1, %2};" : "=l"(r) : "f"(lo), "f"(hi));
    return r;
}
__device__ __forceinline__ void unpack2(ull v, float& lo, float& hi) {
    asm("mov.b64 {%0, %1}, %2;" : "=f"(lo), "=f"(hi) : "l"(v));
}
__device__ __forceinline__ ull fma2(ull a, ull b, ull c) {
    ull d;
    asm("fma.rn.f32x2 %0, %1, %2, %3;" : "=l"(d) : "l"(a), "l"(b), "l"(c));
    return d;
}
__device__ __forceinline__ ull add2(ull a, ull b) {
    ull d;
    asm("add.rn.f32x2 %0, %1, %2;" : "=l"(d) : "l"(a), "l"(b));
    return d;
}

// exp(-0.1*sqrt(max(v,1e-6))) ; always in (0,1] so the clip is free
__device__ __forceinline__ float gauss1(float v) {
    float t = fmaxf(v, 1e-6f);
    float d;
    asm("sqrt.approx.f32 %0, %1;" : "=f"(d) : "f"(t));
    float xx = d * -0.14426950408889634f;   // -0.1 * log2(e)
    float e;
    asm("ex2.approx.f32 %0, %1;" : "=f"(e) : "f"(xx));
    return e;
}

__global__ void __launch_bounds__(NTHREADS, 2)
npg_sym128(const float* __restrict__ x, const float* __restrict__ msk,
           float* __restrict__ out) {
    __shared__ __align__(16) float sRowD[F * RDS];    // rows, duplicated (a,a)
    __shared__ __align__(16) float sCol[F * CS];      // cols, plain
    __shared__ __align__(16) float sNaRD[2 * TE + 4]; // na rows, duplicated
    __shared__ __align__(16) float sNaC[TE + 4];      // na cols, plain
    __shared__ __align__(16) float sXS[32 * XS];      // transpose strip

    const int tid = threadIdx.x;
    const int bk  = blockIdx.y;

    // decode upper-triangular pair (ti <= tj) of the 4x4 tile grid (10 pairs)
    int t = blockIdx.x, ti = 0;
    while (t >= 4 - ti) { t -= 4 - ti; ++ti; }
    const int tj = ti + t;
    const int rbase = ti * TE;
    const int cbase = tj * TE;

    // ---- stage A = x*msk: 128-row slice (duplicated) + 128-col slice ----
    const float4* xb = reinterpret_cast<const float4*>(x + (size_t)bk * NN * F);
    const float*  mb = msk + (size_t)bk * NN;
    #pragma unroll
    for (int k = 0; k < 2; k++) {
        int i  = k * NTHREADS + tid;    // float4 index in 128x16 slice
        int n  = i >> 2;
        int fq = i & 3;
        int f0 = fq << 2;

        float4 v = __ldg(&xb[(rbase + n) * 4 + fq]);
        float  m = __ldg(&mb[rbase + n]);
        float r0 = v.x * m, r1 = v.y * m, r2 = v.z * m, r3 = v.w * m;
        *reinterpret_cast<ull*>(&sRowD[(f0 + 0) * RDS + 2 * n]) = pack2(r0, r0);
        *reinterpret_cast<ull*>(&sRowD[(f0 + 1) * RDS + 2 * n]) = pack2(r1, r1);
        *reinterpret_cast<ull*>(&sRowD[(f0 + 2) * RDS + 2 * n]) = pack2(r2, r2);
        *reinterpret_cast<ull*>(&sRowD[(f0 + 3) * RDS + 2 * n]) = pack2(r3, r3);

        float4 w  = __ldg(&xb[(cbase + n) * 4 + fq]);
        float  mc = __ldg(&mb[cbase + n]);
        sCol[(f0 + 0) * CS + n] = w.x * mc;
        sCol[(f0 + 1) * CS + n] = w.y * mc;
        sCol[(f0 + 2) * CS + n] = w.z * mc;
        sCol[(f0 + 3) * CS + n] = w.w * mc;
    }
    __syncthreads();

    // ---- na for both slices ----
    if (tid < TE) {
        float s = 0.f;
        #pragma unroll
        for (int f = 0; f < F; f++) {
            float a = sRowD[f * RDS + 2 * tid];
            s = fmaf(a, a, s);
        }
        *reinterpret_cast<ull*>(&sNaRD[2 * tid]) = pack2(s, s);
    } else {
        int n = tid - TE;
        float s = 0.f;
        #pragma unroll
        for (int f = 0; f < F; f++) {
            float a = sCol[f * CS + n];
            s = fmaf(a, a, s);
        }
        sNaC[n] = s;
    }
    __syncthreads();

    const int cx = tid & 31;      // 32 col-threads * 4 cols = 128
    const int ry = tid >> 5;      // 8 row-groups * 16 rows = 128 (warp-uniform)
    const int c0 = 4 * cx;

    // ---- cache 4 cols x 16 f as packed pairs (direct 16B loads) ----
    ull ccA[F], ccB[F];
    #pragma unroll
    for (int f = 0; f < F; f++) {
        ull2_t u = *reinterpret_cast<const ull2_t*>(&sCol[f * CS + c0]);
        ccA[f] = u.x;
        ccB[f] = u.y;
    }
    ull nacA, nacB;
    {
        ull2_t u = *reinterpret_cast<const ull2_t*>(&sNaC[c0]);
        nacA = u.x;
        nacB = u.y;
    }

    float* outb = out + (size_t)bk * NN * NN;
    const ull NEG2 = pack2(-2.f, -2.f);
    const int rowBase = ry * 16;

    // ---- 16 rows x 4 cols, two rows in flight (4 indep fma2 chains) ----
    #pragma unroll 1
    for (int i = 0; i < 16; i += 2) {
        const int r0 = rowBase + i;
        ull nar0 = *reinterpret_cast<const ull*>(&sNaRD[2 * r0]);
        ull nar1 = *reinterpret_cast<const ull*>(&sNaRD[2 * r0 + 2]);
        ull s0A = add2(nar0, nacA), s0B = add2(nar0, nacB);
        ull s1A = add2(nar1, nacA), s1B = add2(nar1, nacB);

        ull a00 = 0ULL, a01 = 0ULL, a10 = 0ULL, a11 = 0ULL;
        #pragma unroll
        for (int f = 0; f < F; f++) {
            ull w0 = *reinterpret_cast<const ull*>(&sRowD[f * RDS + 2 * r0]);      // (a,a) broadcast
            ull w1 = *reinterpret_cast<const ull*>(&sRowD[f * RDS + 2 * r0 + 2]);
            a00 = fma2(w0, ccA[f], a00);
            a01 = fma2(w0, ccB[f], a01);
            a10 = fma2(w1, ccA[f], a10);
            a11 = fma2(w1, ccB[f], a11);
        }

        ull v0A = fma2(a00, NEG2, s0A);
        ull v0B = fma2(a01, NEG2, s0B);
        ull v1A = fma2(a10, NEG2, s1A);
        ull v1B = fma2(a11, NEG2, s1B);

        float p0, p1, p2, p3, q0, q1, q2, q3;
        unpack2(v0A, p0, p1);
        unpack2(v0B, p2, p3);
        unpack2(v1A, q0, q1);
        unpack2(v1B, q2, q3);

        float4 o0, o1;
        o0.x = gauss1(p0); o0.y = gauss1(p1); o0.z = gauss1(p2); o0.w = gauss1(p3);
        o1.x = gauss1(q0); o1.y = gauss1(q1); o1.z = gauss1(q2); o1.w = gauss1(q3);

        *reinterpret_cast<float4*>(&outb[(size_t)(rbase + r0) * NN + cbase + c0])     = o0;
        *reinterpret_cast<float4*>(&outb[(size_t)(rbase + r0 + 1) * NN + cbase + c0]) = o1;
    }

    // ---- mirror: re-read own (L2-hot) tile, transpose via smem strips ----
    if (ti != tj) {
        __syncthreads();   // straight writes visible block-wide
        #pragma unroll 1
        for (int bi = 0; bi < 4; bi++) {
            // load strip: rows [rbase+32*bi, +32) x cols [cbase, +128)
            #pragma unroll
            for (int it = 0; it < 16; it++) {
                int idx = it * NTHREADS + tid;
                int rr = idx >> 7, c = idx & 127;     // coalesced 128B/warp
                sXS[rr * XS + c] =
                    outb[(size_t)(rbase + 32 * bi + rr) * NN + cbase + c];
            }
            __syncthreads();
            // write transposed: mirror rows = cols, coalesced
            #pragma unroll
            for (int it = 0; it < 16; it++) {
                int idx = it * NTHREADS + tid;
                int cc = idx >> 5, rr = idx & 31;     // bank (5*rr+cc): conflict-free
                outb[(size_t)(cbase + cc) * NN + rbase + 32 * bi + rr] =
                    sXS[rr * XS + cc];
            }
            __syncthreads();
        }
    }
}

extern "C" void kernel_launch(void* const* d_in, const int* in_sizes, int n_in,
                              void* d_out, int out_size) {
    const float* x   = (const float*)d_in[0];   // (8,64,512,16)
    const float* msk = (const float*)d_in[1];   // (8,64,512,1)
    float* out = (float*)d_out;                 // (8,64,512,512,1)

    int bk_total = in_sizes[0] / (NN * F);      // 512
    dim3 grid(10, bk_total);                    // 10 upper-tri 128-tiles x 512 bins
    npg_sym128<<<grid, NTHREADS>>>(x, msk, out);
}